// round 8
// baseline (speedup 1.0000x reference)
#include <cuda_runtime.h>
#include <cuda_fp16.h>
#include <cstdint>

#define N_TOK    65536
#define KCODES   8192
#define ZQ_ELEMS 4194304
#define NT       256
#define NCH      64          // 4096 codes per half / 64 per chunk
#define ACC_TH   2.4f        // rescore window, acc units (= 5.9e-4 dd; ~7 sigma of fp8 key err)
#define FLT_BIG  3.402823e38f

// ---- smem layout (bytes) ----
#define SOFF_Z   0           // 32768 : z tile [d64][m128] fp32 (kept live for rescore)
#define SOFF_B   32768       // 8192  : B e4m3 frags [buf2][1024 words]
#define SOFF_EN  40960       // 2*64*4
#define SOFF_ZN  41472       // 128*4
#define SMEM_SZ  41984
#define BWORDS   1024        // 32-bit words per buffer

__device__ float              g_enorm[KCODES];
__device__ unsigned long long g_best[N_TOK];
__device__ float              g_loss;

__device__ __forceinline__ uint32_t pack4e(float a, float b, float c, float d){
    // byte0 = a (lowest k), byte3 = d
    uint16_t lo, hi;
    asm("cvt.rn.satfinite.e4m3x2.f32 %0, %1, %2;" : "=h"(lo) : "f"(b), "f"(a));
    asm("cvt.rn.satfinite.e4m3x2.f32 %0, %1, %2;" : "=h"(hi) : "f"(d), "f"(c));
    return (uint32_t)lo | ((uint32_t)hi << 16);
}
__device__ __forceinline__ void mma_fp8(float* d, const uint32_t* a, uint32_t b0, uint32_t b1){
    asm volatile("mma.sync.aligned.m16n8k32.row.col.f32.e4m3.e4m3.f32 "
        "{%0,%1,%2,%3}, {%4,%5,%6,%7}, {%8,%9}, {%0,%1,%2,%3};"
        : "+f"(d[0]), "+f"(d[1]), "+f"(d[2]), "+f"(d[3])
        : "r"(a[0]), "r"(a[1]), "r"(a[2]), "r"(a[3]), "r"(b0), "r"(b1));
}
__device__ __forceinline__ unsigned long long packbi(float dd, int idx){
    uint32_t u = __float_as_uint(dd);
    u = (u & 0x80000000u) ? ~u : (u | 0x80000000u);
    return ((unsigned long long)u << 32) | (uint32_t)idx;
}

// ---------------------------------------------------------------------------
// K1: ||e_k||^2 (sequential fmaf, d ascending), init g_best, zero loss
// ---------------------------------------------------------------------------
__global__ void vq_pre(const float* __restrict__ emb){
    int t = blockIdx.x * 256 + threadIdx.x;
    if (t < KCODES){
        const float4* r = (const float4*)(emb + t*64);
        float s = 0.f;
        #pragma unroll
        for (int i = 0; i < 16; i++){
            float4 v = __ldg(&r[i]);
            s = fmaf(v.x,v.x,s); s = fmaf(v.y,v.y,s); s = fmaf(v.z,v.z,s); s = fmaf(v.w,v.w,s);
        }
        g_enorm[t] = s;
    }
    if (t < N_TOK) g_best[t] = 0xFFFFFFFFFFFFFFFFull;
    if (t == 0) g_loss = 0.f;
}

// ---------------------------------------------------------------------------
// K2: e4m3 QMMA screen (B scaled 2^13), fp32 acc, per-lane top-6 +
//     exact fp32 rescore + atomicMin merge.
// grid (512 token tiles, 2 code halves); CTA = 128 tokens x 4096 codes.
// ---------------------------------------------------------------------------
__global__ __launch_bounds__(NT, 2) void vq_main(const float* __restrict__ z,
                                                 const float* __restrict__ emb){
    extern __shared__ __align__(16) char smem[];
    float*    zS  = (float*)(smem + SOFF_Z);
    uint32_t* Bs  = (uint32_t*)(smem + SOFF_B);
    float*    enS = (float*)(smem + SOFF_EN);
    float*    znS = (float*)(smem + SOFF_ZN);

    int tid = threadIdx.x, wid = tid >> 5, lane = tid & 31;
    int n0 = blockIdx.x * 128;
    int kbase = blockIdx.y * 4096;
    const float* zb = z + (n0 >> 12) * 262144 + (n0 & 4095);

    for (int i = tid; i < 64*128; i += NT){
        int d = i >> 7, m = i & 127;
        zS[d*128 + m] = zb[d*4096 + m];
    }
    __syncthreads();

    if (tid < 128){
        float s = 0.f;
        #pragma unroll
        for (int d = 0; d < 64; d++){ float v = zS[d*128 + tid]; s = fmaf(v, v, s); }
        znS[tid] = s;
    }

    // A fragments in registers (loop-invariant): e4m3, K=64 -> 2 ks-steps x 4 regs
    uint32_t Af[2][4];
    {
        int r0 = wid*16 + (lane >> 2);
        #pragma unroll
        for (int ks = 0; ks < 2; ks++){
            int kk = ks*32 + (lane & 3)*4;
            #pragma unroll
            for (int h = 0; h < 2; h++){       // h: +16 k offset (regs 2,3)
                int kq = kk + h*16;
                Af[ks][h*2+0] = pack4e(zS[(kq  )*128 + r0  ], zS[(kq+1)*128 + r0  ],
                                       zS[(kq+2)*128 + r0  ], zS[(kq+3)*128 + r0  ]);
                Af[ks][h*2+1] = pack4e(zS[(kq  )*128 + r0+8], zS[(kq+1)*128 + r0+8],
                                       zS[(kq+2)*128 + r0+8], zS[(kq+3)*128 + r0+8]);
            }
        }
    }

    // B producer: float4 (code n, dims d0..d0+3) -> one e4m3x4 word
    auto bword = [](int n, int d0) -> int {
        int nt = n >> 3, ks = d0 >> 5, p = (d0 >> 4) & 1;
        int L = (n & 7)*4 + ((d0 >> 2) & 3);
        return ((nt*2 + ks)*32 + L)*2 + p;
    };

    // produce chunk 0 into buffer 0
    {
        const float4* src = (const float4*)(emb + (size_t)kbase*64);
        #pragma unroll
        for (int j = 0; j < 4; j++){
            int f = j*256 + tid;
            float4 v = __ldg(&src[f]);
            int n = f >> 4, d0 = (f & 15)*4;
            Bs[bword(n, d0)] = pack4e(v.x*8192.f, v.y*8192.f, v.z*8192.f, v.w*8192.f);
        }
        if (tid < 64) enS[tid] = __ldg(&g_enorm[kbase + tid]);
    }
    __syncthreads();

    // top-6 per lane, 2 rows (acc domain: larger = better)
    float s0[6], s1[6]; int ix0[6], ix1[6];
    #pragma unroll
    for (int j = 0; j < 6; j++){ s0[j] = -FLT_BIG; s1[j] = -FLT_BIG; ix0[j] = 0; ix1[j] = 0; }

    auto ins6 = [](float (&s)[6], int (&ix)[6], float v, int kk){
        if (v > s[5]){
            int pos = 5;
            if      (v > s[0]) pos = 0;
            else if (v > s[1]) pos = 1;
            else if (v > s[2]) pos = 2;
            else if (v > s[3]) pos = 3;
            else if (v > s[4]) pos = 4;
            #pragma unroll
            for (int t = 5; t > 0; t--){
                if (t > pos){ s[t] = s[t-1]; ix[t] = ix[t-1]; }
            }
            s[pos] = v; ix[pos] = kk;
        }
    };

    #pragma unroll 1
    for (int c = 0; c < NCH; c++){
        int buf = c & 1;
        float4 pv[4];
        bool more = (c + 1 < NCH);
        if (more){
            const float4* src = (const float4*)(emb + (size_t)(kbase + (c+1)*64)*64);
            #pragma unroll
            for (int j = 0; j < 4; j++) pv[j] = __ldg(&src[j*256 + tid]);
        }

        // acc init: -4096*en  (acc = 8192*dot - 4096*en = -4096*(en - 2*dot))
        float acc[8][4];
        #pragma unroll
        for (int nt = 0; nt < 8; nt++){
            int c0 = nt*8 + (lane & 3)*2;
            float2 en2 = *(const float2*)&enS[buf*64 + c0];
            acc[nt][0] = en2.x * -4096.f; acc[nt][1] = en2.y * -4096.f;
            acc[nt][2] = acc[nt][0];      acc[nt][3] = acc[nt][1];
        }

        const uint2* Bb = (const uint2*)(Bs + buf*BWORDS);
        #pragma unroll
        for (int ks = 0; ks < 2; ks++){
            #pragma unroll
            for (int nt = 0; nt < 8; nt++){
                uint2 b = Bb[(nt*2 + ks)*32 + lane];
                mma_fp8(acc[nt], Af[ks], b.x, b.y);
            }
        }

        // epilogue: guarded top-6 insert (ascending code order)
        int kk0 = kbase + c*64;
        #pragma unroll
        for (int nt = 0; nt < 8; nt++){
            int c0 = nt*8 + (lane & 3)*2;
            int kA = kk0 + c0, kB = kA + 1;
            if (fmaxf(acc[nt][0], acc[nt][1]) > s0[5]){
                ins6(s0, ix0, acc[nt][0], kA); ins6(s0, ix0, acc[nt][1], kB);
            }
            if (fmaxf(acc[nt][2], acc[nt][3]) > s1[5]){
                ins6(s1, ix1, acc[nt][2], kA); ins6(s1, ix1, acc[nt][3], kB);
            }
        }

        if (more){
            uint32_t* BW = Bs + (buf^1)*BWORDS;
            #pragma unroll
            for (int j = 0; j < 4; j++){
                int f = j*256 + tid;
                int n = f >> 4, d0 = (f & 15)*4;
                BW[bword(n, d0)] = pack4e(pv[j].x*8192.f, pv[j].y*8192.f,
                                          pv[j].z*8192.f, pv[j].w*8192.f);
            }
            if (tid < 64) enS[(buf^1)*64 + tid] = __ldg(&g_enorm[kbase + (c+1)*64 + tid]);
        }
        __syncthreads();
    }

    // quad max then exact fp32 rescore of all within-window candidates
    float q0 = s0[0], q1 = s1[0];
    #pragma unroll
    for (int off = 1; off <= 2; off <<= 1){
        q0 = fmaxf(q0, __shfl_xor_sync(0xFFFFFFFF, q0, off));
        q1 = fmaxf(q1, __shfl_xor_sync(0xFFFFFFFF, q1, off));
    }
    float thr0 = q0 - ACC_TH, thr1 = q1 - ACC_TH;
    int r0 = wid*16 + (lane >> 2);
    float zn0 = znS[r0], zn1 = znS[r0 + 8];

    auto rescore = [&](int rloc, float sv, int idx, float thr, float zn){
        if (sv >= thr){
            const float4* ep = (const float4*)(emb + idx*64);
            float dot = 0.f;
            #pragma unroll 4
            for (int q = 0; q < 16; q++){
                float4 ev = __ldg(&ep[q]);
                int d = q*4;
                dot = fmaf(zS[(d  )*128 + rloc], ev.x, dot);
                dot = fmaf(zS[(d+1)*128 + rloc], ev.y, dot);
                dot = fmaf(zS[(d+2)*128 + rloc], ev.z, dot);
                dot = fmaf(zS[(d+3)*128 + rloc], ev.w, dot);
            }
            float dd = fmaf(-2.f, dot, zn + __ldg(&g_enorm[idx]));   // exact (R2-validated) formula
            atomicMin(&g_best[n0 + rloc], packbi(dd, idx));
        }
    };
    #pragma unroll
    for (int j = 0; j < 6; j++){
        rescore(r0,     s0[j], ix0[j], thr0, zn0);
        rescore(r0 + 8, s1[j], ix1[j], thr1, zn1);
    }
}

// ---------------------------------------------------------------------------
// K3: gather z_q, straight-through output, loss partial, index output
// ---------------------------------------------------------------------------
__global__ void vq_out(const float* __restrict__ z, const float* __restrict__ emb,
                       float* __restrict__ outz, float* __restrict__ outIdxF, int writeF){
    int tid = threadIdx.x;
    int n0 = blockIdx.x * 64;
    const int b = n0 >> 12; const int hw0 = n0 & 4095;
    const float* zb = z    + b*262144 + hw0;
    float*       ob = outz + b*262144 + hw0;

    __shared__ int idxs[64];
    if (tid < 64){
        int idx = (int)(g_best[n0 + tid] & 0xFFFFFFFFull);
        idxs[tid] = idx;
        if (writeF) outIdxF[n0 + tid] = (float)idx;
    }
    __syncthreads();

    float ls = 0.f;
    for (int i = tid; i < 64*64; i += 256){
        int c = i >> 6, m = i & 63;
        float e  = __ldg(&emb[idxs[m]*64 + c]);
        float zv = zb[c*4096 + m];
        float t  = e - zv;
        ob[c*4096 + m] = zv + t;      // fl(zc + fl(zq - zc)) — STE rounding replicated
        ls = fmaf(t, t, ls);
    }
    __shared__ float red[256];
    red[tid] = ls; __syncthreads();
    for (int s = 128; s > 0; s >>= 1){
        if (tid < s) red[tid] += red[tid + s];
        __syncthreads();
    }
    if (tid == 0) atomicAdd(&g_loss, red[0]);
}

__global__ void vq_fin(float* __restrict__ out, int full){
    if (full){
        float m = g_loss * (1.f / (float)ZQ_ELEMS);
        out[ZQ_ELEMS] = m + 0.25f * m;
    }
}

// ---------------------------------------------------------------------------
extern "C" void kernel_launch(void* const* d_in, const int* in_sizes, int n_in,
                              void* d_out, int out_size){
    const float* z   = (const float*)d_in[0];
    const float* emb = (const float*)d_in[1];
    float* out = (float*)d_out;

    int full = (out_size >= ZQ_ELEMS + 1 + N_TOK) ? 1 : 0;

    cudaFuncSetAttribute(vq_main, cudaFuncAttributeMaxDynamicSharedMemorySize, SMEM_SZ);

    vq_pre<<<N_TOK/256, 256>>>(emb);
    dim3 grid(N_TOK/128, 2);
    vq_main<<<grid, NT, SMEM_SZ>>>(z, emb);
    vq_out<<<N_TOK/64, 256>>>(z, emb, out, full ? (out + ZQ_ELEMS + 1) : out, full);
    vq_fin<<<1, 1>>>(out, full);
}

// round 9
// speedup vs baseline: 1.6186x; 1.6186x over previous
#include <cuda_runtime.h>
#include <cstdint>

#define N_TOK    65536
#define KCODES   8192
#define ZQ_ELEMS 4194304
#define NT       256
#define NCH      64          // 4096 codes per half / 64 per chunk
#define TH_DD    1.0e-4f     // rescore window in dd units (~7 sigma of int8 key err)
#define S_E      1040384.f   // 127*8192: e in (-1/8192,1/8192) -> never clips
#define FLT_BIG  3.402823e38f

// ---- smem layout (bytes) ----
#define SOFF_Z   0           // 32768 : z tile [d64][m128] fp32 (kept live for rescore)
#define SOFF_B   32768       // 8192  : B s8 frags [buf2][1024 words]
#define SOFF_EN  40960       // 2*64*4
#define SOFF_ZN  41472       // 128*4
#define SOFF_RS  41984       // 128*4 : per-row scale S_m
#define SMEM_SZ  42496
#define BWORDS   1024        // 32-bit words per buffer

__device__ float              g_enorm[KCODES];
__device__ unsigned long long g_best[N_TOK];
__device__ float              g_loss;

__device__ __forceinline__ uint32_t pack4s(float a, float b, float c, float d, float S){
    int i0 = __float2int_rn(a*S), i1 = __float2int_rn(b*S);
    int i2 = __float2int_rn(c*S), i3 = __float2int_rn(d*S);
    return (uint32_t)(i0 & 255) | ((uint32_t)(i1 & 255) << 8)
         | ((uint32_t)(i2 & 255) << 16) | ((uint32_t)i3 << 24);
}
__device__ __forceinline__ void mma_s8(int* d, const uint32_t* a, uint32_t b0, uint32_t b1){
    asm volatile("mma.sync.aligned.m16n8k32.row.col.s32.s8.s8.s32 "
        "{%0,%1,%2,%3}, {%4,%5,%6,%7}, {%8,%9}, {%0,%1,%2,%3};"
        : "+r"(d[0]), "+r"(d[1]), "+r"(d[2]), "+r"(d[3])
        : "r"(a[0]), "r"(a[1]), "r"(a[2]), "r"(a[3]), "r"(b0), "r"(b1));
}
__device__ __forceinline__ unsigned long long packbi(float dd, int idx){
    uint32_t u = __float_as_uint(dd);
    u = (u & 0x80000000u) ? ~u : (u | 0x80000000u);
    return ((unsigned long long)u << 32) | (uint32_t)idx;
}

// ---------------------------------------------------------------------------
// K1: ||e_k||^2 (sequential fmaf, d ascending), init g_best, zero loss
// ---------------------------------------------------------------------------
__global__ void vq_pre(const float* __restrict__ emb){
    int t = blockIdx.x * 256 + threadIdx.x;
    if (t < KCODES){
        const float4* r = (const float4*)(emb + t*64);
        float s = 0.f;
        #pragma unroll
        for (int i = 0; i < 16; i++){
            float4 v = __ldg(&r[i]);
            s = fmaf(v.x,v.x,s); s = fmaf(v.y,v.y,s); s = fmaf(v.z,v.z,s); s = fmaf(v.w,v.w,s);
        }
        g_enorm[t] = s;
    }
    if (t < N_TOK) g_best[t] = 0xFFFFFFFFFFFFFFFFull;
    if (t == 0) g_loss = 0.f;
}

// ---------------------------------------------------------------------------
// K2: s8 IMMA screen (per-row A scale, exact int32 acc), per-lane top-4 +
//     exact fp32 rescore + atomicMin merge.
// grid (512 token tiles, 2 code halves); CTA = 128 tokens x 4096 codes.
// ---------------------------------------------------------------------------
__global__ __launch_bounds__(NT, 2) void vq_main(const float* __restrict__ z,
                                                 const float* __restrict__ emb){
    extern __shared__ __align__(16) char smem[];
    float*    zS  = (float*)(smem + SOFF_Z);
    uint32_t* Bs  = (uint32_t*)(smem + SOFF_B);
    float*    enS = (float*)(smem + SOFF_EN);
    float*    znS = (float*)(smem + SOFF_ZN);
    float*    rsS = (float*)(smem + SOFF_RS);

    int tid = threadIdx.x, wid = tid >> 5, lane = tid & 31;
    int n0 = blockIdx.x * 128;
    int kbase = blockIdx.y * 4096;
    const float* zb = z + (n0 >> 12) * 262144 + (n0 & 4095);

    for (int i = tid; i < 64*128; i += NT){
        int d = i >> 7, m = i & 127;
        zS[d*128 + m] = zb[d*4096 + m];
    }
    __syncthreads();

    // zn (sequential fmaf, d ascending) + per-row scale
    if (tid < 128){
        float s = 0.f, mx = 1e-30f;
        #pragma unroll
        for (int d = 0; d < 64; d++){
            float v = zS[d*128 + tid];
            s = fmaf(v, v, s);
            mx = fmaxf(mx, fabsf(v));
        }
        znS[tid] = s;
        rsS[tid] = 126.f / mx;
    }
    __syncthreads();

    int r0 = wid*16 + (lane >> 2);
    float S0 = rsS[r0], S1 = rsS[r0 + 8];
    float fac0 = S0 * (S_E * 0.5f), fac1 = S1 * (S_E * 0.5f);
    int TH0 = __float2int_rn(TH_DD * fac0) + 2;
    int TH1 = __float2int_rn(TH_DD * fac1) + 2;

    // A fragments in registers (loop-invariant): s8, K=64 -> 2 ks-steps x 4 regs
    uint32_t Af[2][4];
    #pragma unroll
    for (int ks = 0; ks < 2; ks++){
        int kk = ks*32 + (lane & 3)*4;
        #pragma unroll
        for (int h = 0; h < 2; h++){       // h: +16 k offset (regs 2,3)
            int kq = kk + h*16;
            Af[ks][h*2+0] = pack4s(zS[(kq  )*128 + r0  ], zS[(kq+1)*128 + r0  ],
                                   zS[(kq+2)*128 + r0  ], zS[(kq+3)*128 + r0  ], S0);
            Af[ks][h*2+1] = pack4s(zS[(kq  )*128 + r0+8], zS[(kq+1)*128 + r0+8],
                                   zS[(kq+2)*128 + r0+8], zS[(kq+3)*128 + r0+8], S1);
        }
    }

    // B word index: (code n, dims d0..d0+3) -> one s8x4 word
    auto bword = [](int n, int d0) -> int {
        int nt = n >> 3, ks = d0 >> 5, p = (d0 >> 4) & 1;
        int L = (n & 7)*4 + ((d0 >> 2) & 3);
        return ((nt*2 + ks)*32 + L)*2 + p;
    };

    // produce chunk 0 into buffer 0
    {
        const float4* src = (const float4*)(emb + (size_t)kbase*64);
        #pragma unroll
        for (int j = 0; j < 4; j++){
            int f = j*256 + tid;
            float4 v = __ldg(&src[f]);
            int n = f >> 4, d0 = (f & 15)*4;
            Bs[bword(n, d0)] = pack4s(v.x, v.y, v.z, v.w, S_E);
        }
        if (tid < 64) enS[tid] = __ldg(&g_enorm[kbase + tid]);
    }
    __syncthreads();

    // top-4 per lane, 2 rows (int acc domain: larger = better)
    int s0[4], s1[4], ix0[4], ix1[4];
    #pragma unroll
    for (int j = 0; j < 4; j++){ s0[j] = -2147483647; s1[j] = -2147483647; ix0[j] = 0; ix1[j] = 0; }

    auto ins4 = [](int (&s)[4], int (&ix)[4], int v, int kk){
        if (v > s[3]){
            int pos = 3;
            if      (v > s[0]) pos = 0;
            else if (v > s[1]) pos = 1;
            else if (v > s[2]) pos = 2;
            #pragma unroll
            for (int t = 3; t > 0; t--){
                if (t > pos){ s[t] = s[t-1]; ix[t] = ix[t-1]; }
            }
            s[pos] = v; ix[pos] = kk;
        }
    };

    #pragma unroll 1
    for (int c = 0; c < NCH; c++){
        int buf = c & 1;
        float4 pv[4];
        bool more = (c + 1 < NCH);
        if (more){
            const float4* src = (const float4*)(emb + (size_t)(kbase + (c+1)*64)*64);
            #pragma unroll
            for (int j = 0; j < 4; j++) pv[j] = __ldg(&src[j*256 + tid]);
        }

        // acc init: -rn(en * S_m*S_e/2)  => acc_final = -(en - 2*dot)*fac (argmax == argmin d)
        int acc[8][4];
        #pragma unroll
        for (int nt = 0; nt < 8; nt++){
            int c0 = nt*8 + (lane & 3)*2;
            float2 en2 = *(const float2*)&enS[buf*64 + c0];
            acc[nt][0] = -__float2int_rn(en2.x * fac0);
            acc[nt][1] = -__float2int_rn(en2.y * fac0);
            acc[nt][2] = -__float2int_rn(en2.x * fac1);
            acc[nt][3] = -__float2int_rn(en2.y * fac1);
        }

        const uint2* Bb = (const uint2*)(Bs + buf*BWORDS);
        #pragma unroll
        for (int ks = 0; ks < 2; ks++){
            #pragma unroll
            for (int nt = 0; nt < 8; nt++){
                uint2 b = Bb[(nt*2 + ks)*32 + lane];
                mma_s8(acc[nt], Af[ks], b.x, b.y);
            }
        }

        // wait — acc rows share A-regs but rows have different scales; regs 0,1 are row r0
        // (packed with S0) and regs 2,3 row r0+8 (packed with S1): consistent by construction.

        // epilogue: guarded top-4 insert (ascending code order)
        int kk0 = kbase + c*64;
        #pragma unroll
        for (int nt = 0; nt < 8; nt++){
            int c0 = nt*8 + (lane & 3)*2;
            int kA = kk0 + c0, kB = kA + 1;
            if (max(acc[nt][0], acc[nt][1]) > s0[3]){
                ins4(s0, ix0, acc[nt][0], kA); ins4(s0, ix0, acc[nt][1], kB);
            }
            if (max(acc[nt][2], acc[nt][3]) > s1[3]){
                ins4(s1, ix1, acc[nt][2], kA); ins4(s1, ix1, acc[nt][3], kB);
            }
        }

        if (more){
            uint32_t* BW = Bs + (buf^1)*BWORDS;
            #pragma unroll
            for (int j = 0; j < 4; j++){
                int f = j*256 + tid;
                int n = f >> 4, d0 = (f & 15)*4;
                BW[bword(n, d0)] = pack4s(pv[j].x, pv[j].y, pv[j].z, pv[j].w, S_E);
            }
            if (tid < 64) enS[(buf^1)*64 + tid] = __ldg(&g_enorm[kbase + (c+1)*64 + tid]);
        }
        __syncthreads();
    }

    // quad max then exact fp32 rescore of all within-window candidates
    int q0 = s0[0], q1 = s1[0];
    #pragma unroll
    for (int off = 1; off <= 2; off <<= 1){
        q0 = max(q0, __shfl_xor_sync(0xFFFFFFFF, q0, off));
        q1 = max(q1, __shfl_xor_sync(0xFFFFFFFF, q1, off));
    }
    int thr0 = q0 - TH0, thr1 = q1 - TH1;
    float zn0 = znS[r0], zn1 = znS[r0 + 8];

    auto rescore = [&](int rloc, int sv, int idx, int thr, float zn){
        if (sv >= thr){
            const float4* ep = (const float4*)(emb + idx*64);
            float dot = 0.f;
            #pragma unroll 4
            for (int q = 0; q < 16; q++){
                float4 ev = __ldg(&ep[q]);
                int d = q*4;
                dot = fmaf(zS[(d  )*128 + rloc], ev.x, dot);
                dot = fmaf(zS[(d+1)*128 + rloc], ev.y, dot);
                dot = fmaf(zS[(d+2)*128 + rloc], ev.z, dot);
                dot = fmaf(zS[(d+3)*128 + rloc], ev.w, dot);
            }
            float dd = fmaf(-2.f, dot, zn + __ldg(&g_enorm[idx]));   // exact (R2-validated) formula
            atomicMin(&g_best[n0 + rloc], packbi(dd, idx));
        }
    };
    #pragma unroll
    for (int j = 0; j < 4; j++){
        rescore(r0,     s0[j], ix0[j], thr0, zn0);
        rescore(r0 + 8, s1[j], ix1[j], thr1, zn1);
    }
}

// ---------------------------------------------------------------------------
// K3: gather z_q, straight-through output, loss partial, index output
// ---------------------------------------------------------------------------
__global__ void vq_out(const float* __restrict__ z, const float* __restrict__ emb,
                       float* __restrict__ outz, float* __restrict__ outIdxF, int writeF){
    int tid = threadIdx.x;
    int n0 = blockIdx.x * 64;
    const int b = n0 >> 12; const int hw0 = n0 & 4095;
    const float* zb = z    + b*262144 + hw0;
    float*       ob = outz + b*262144 + hw0;

    __shared__ int idxs[64];
    if (tid < 64){
        int idx = (int)(g_best[n0 + tid] & 0xFFFFFFFFull);
        idxs[tid] = idx;
        if (writeF) outIdxF[n0 + tid] = (float)idx;
    }
    __syncthreads();

    float ls = 0.f;
    for (int i = tid; i < 64*64; i += 256){
        int c = i >> 6, m = i & 63;
        float e  = __ldg(&emb[idxs[m]*64 + c]);
        float zv = zb[c*4096 + m];
        float t  = e - zv;
        ob[c*4096 + m] = zv + t;      // fl(zc + fl(zq - zc)) — STE rounding replicated
        ls = fmaf(t, t, ls);
    }
    __shared__ float red[256];
    red[tid] = ls; __syncthreads();
    for (int s = 128; s > 0; s >>= 1){
        if (tid < s) red[tid] += red[tid + s];
        __syncthreads();
    }
    if (tid == 0) atomicAdd(&g_loss, red[0]);
}

__global__ void vq_fin(float* __restrict__ out, int full){
    if (full){
        float m = g_loss * (1.f / (float)ZQ_ELEMS);
        out[ZQ_ELEMS] = m + 0.25f * m;
    }
}

// ---------------------------------------------------------------------------
extern "C" void kernel_launch(void* const* d_in, const int* in_sizes, int n_in,
                              void* d_out, int out_size){
    const float* z   = (const float*)d_in[0];
    const float* emb = (const float*)d_in[1];
    float* out = (float*)d_out;

    int full = (out_size >= ZQ_ELEMS + 1 + N_TOK) ? 1 : 0;

    cudaFuncSetAttribute(vq_main, cudaFuncAttributeMaxDynamicSharedMemorySize, SMEM_SZ);

    vq_pre<<<N_TOK/256, 256>>>(emb);
    dim3 grid(N_TOK/128, 2);
    vq_main<<<grid, NT, SMEM_SZ>>>(z, emb);
    vq_out<<<N_TOK/64, 256>>>(z, emb, out, full ? (out + ZQ_ELEMS + 1) : out, full);
    vq_fin<<<1, 1>>>(out, full);
}

// round 10
// speedup vs baseline: 2.6194x; 1.6183x over previous
#include <cuda_runtime.h>
#include <cuda_fp16.h>
#include <cstdint>

#define N_TOK    65536
#define KCODES   8192
#define ZQ_ELEMS 4194304
#define NT       384         // 12 warps: 0-7 mma screen, 8-11 exact ffma
#define NCH_T    51          // mma chunks  (3264 codes)
#define NCH_F    13          // ffma chunks (832 codes)
#define KOFF_F   3264
#define ACC_TH   0.4096f     // R6-proven rescore window (acc domain)
#define FLT_BIG  3.402823e38f

// ---- smem layout (bytes) ----
#define SOFF_Z    0          // 32768 : z tile [d64][m128] fp32
#define SOFF_B16  32768      // 16896 : mma B fp16 frags [buf2]
#define SOFF_EN   49664      // 2*64*4
#define SOFF_ZN   50176      // 128*4
#define SOFF_BF   50688      // 34816 : ffma B fp32 [buf2][code64][68]
#define SMEM_SZ   122880     // padded: forces 1 CTA/SM
#define BSTRIDE   2112       // uint32 words per mma B buffer
#define BF_CODES  68         // fp32 row stride (272B, 16B-aligned, conflict-free)

__device__ float              g_enorm[KCODES];
__device__ unsigned long long g_best[N_TOK];
__device__ float              g_loss;

__device__ __forceinline__ uint32_t pack2h(float lo, float hi){
    uint32_t r; asm("cvt.rn.f16x2.f32 %0, %1, %2;" : "=r"(r) : "f"(hi), "f"(lo)); return r;
}
__device__ __forceinline__ void mma_fp16(float* d, const uint32_t* a, uint32_t b0, uint32_t b1){
    asm volatile("mma.sync.aligned.m16n8k16.row.col.f32.f16.f16.f32 "
        "{%0,%1,%2,%3}, {%4,%5,%6,%7}, {%8,%9}, {%0,%1,%2,%3};"
        : "+f"(d[0]), "+f"(d[1]), "+f"(d[2]), "+f"(d[3])
        : "r"(a[0]), "r"(a[1]), "r"(a[2]), "r"(a[3]), "r"(b0), "r"(b1));
}
__device__ __forceinline__ unsigned long long packbi(float dd, int idx){
    uint32_t u = __float_as_uint(dd);
    u = (u & 0x80000000u) ? ~u : (u | 0x80000000u);
    return ((unsigned long long)u << 32) | (uint32_t)idx;
}
#define BAR(id, cnt) asm volatile("bar.sync %0, %1;" :: "r"(id), "r"(cnt) : "memory")
#define CP_ASYNC16(dst, src) asm volatile("cp.async.ca.shared.global [%0], [%1], 16;" :: "r"(dst), "l"(src))
#define CP_COMMIT()  asm volatile("cp.async.commit_group;" ::: "memory")
#define CP_WAIT1()   asm volatile("cp.async.wait_group 1;" ::: "memory")
#define CP_WAIT0()   asm volatile("cp.async.wait_group 0;" ::: "memory")

// ---------------------------------------------------------------------------
// K1: ||e_k||^2 (sequential fmaf, d ascending), init g_best, zero loss
// ---------------------------------------------------------------------------
__global__ void vq_pre(const float* __restrict__ emb){
    int t = blockIdx.x * 256 + threadIdx.x;
    if (t < KCODES){
        const float4* r = (const float4*)(emb + t*64);
        float s = 0.f;
        #pragma unroll
        for (int i = 0; i < 16; i++){
            float4 v = __ldg(&r[i]);
            s = fmaf(v.x,v.x,s); s = fmaf(v.y,v.y,s); s = fmaf(v.z,v.z,s); s = fmaf(v.w,v.w,s);
        }
        g_enorm[t] = s;
    }
    if (t < N_TOK) g_best[t] = 0xFFFFFFFFFFFFFFFFull;
    if (t == 0) g_loss = 0.f;
}

// ---------------------------------------------------------------------------
// K2: dual-pipe. Warps 0-7: fp16 HMMA screen (top-3 + exact rescore) over
// codes [kbase, kbase+3264). Warps 8-11: exact fp32 FFMA distances over
// codes [kbase+3264, kbase+4096). Merge via packed atomicMin.
// ---------------------------------------------------------------------------
__global__ __launch_bounds__(NT, 1) void vq_main(const float* __restrict__ z,
                                                 const float* __restrict__ emb){
    extern __shared__ __align__(16) char smem[];
    float*    zS  = (float*)(smem + SOFF_Z);
    uint32_t* Bs  = (uint32_t*)(smem + SOFF_B16);
    float*    enS = (float*)(smem + SOFF_EN);
    float*    znS = (float*)(smem + SOFF_ZN);
    float*    BfS = (float*)(smem + SOFF_BF);

    int tid = threadIdx.x, wid = tid >> 5, lane = tid & 31;
    int n0 = blockIdx.x * 128;
    int kbase = blockIdx.y * 4096;
    const float* zb = z + (n0 >> 12) * 262144 + (n0 & 4095);

    for (int i = tid; i < 64*128; i += NT){
        int d = i >> 7, m = i & 127;
        zS[d*128 + m] = zb[d*4096 + m];
    }
    __syncthreads();

    if (tid < 128){
        float s = 0.f;
        #pragma unroll
        for (int d = 0; d < 64; d++){ float v = zS[d*128 + tid]; s = fmaf(v, v, s); }
        znS[tid] = s;
    }
    __syncthreads();

    if (wid < 8){
        // =================== MMA screen group (256 threads) ===================
        int r0 = wid*16 + (lane >> 2);
        uint32_t Af[4][4];
        #pragma unroll
        for (int ks = 0; ks < 4; ks++){
            int k0 = ks*16 + (lane & 3)*2;
            Af[ks][0] = pack2h(zS[(k0  )*128 + r0  ], zS[(k0+1)*128 + r0  ]);
            Af[ks][1] = pack2h(zS[(k0  )*128 + r0+8], zS[(k0+1)*128 + r0+8]);
            Af[ks][2] = pack2h(zS[(k0+8)*128 + r0  ], zS[(k0+9)*128 + r0  ]);
            Af[ks][3] = pack2h(zS[(k0+8)*128 + r0+8], zS[(k0+9)*128 + r0+8]);
        }

        // produce chunk 0 into buffer 0
        {
            const float4* src = (const float4*)(emb + (size_t)kbase*64);
            #pragma unroll
            for (int j = 0; j < 4; j++){
                int f = j*256 + tid;
                float4 v = __ldg(&src[f]);
                int n = f >> 4, k0 = (f & 15)*4;
                uint32_t u0 = pack2h(v.x*8192.f, v.y*8192.f);
                uint32_t u1 = pack2h(v.z*8192.f, v.w*8192.f);
                int nt = n >> 3, ks = k0 >> 4, p = (k0 >> 3) & 1;
                int Lt = (n & 7)*4 + ((k0 & 7) >> 1);
                uint32_t* dst = Bs + ((nt*4 + ks)*33 + Lt)*2 + p;
                dst[0] = u0; dst[2] = u1;
            }
            if (tid < 64) enS[tid] = __ldg(&g_enorm[kbase + tid]);
        }
        BAR(1, 256);

        float s0[3], s1[3]; int ix0[3], ix1[3];
        #pragma unroll
        for (int j = 0; j < 3; j++){ s0[j] = -FLT_BIG; s1[j] = -FLT_BIG; ix0[j] = 0; ix1[j] = 0; }

        auto ins3 = [](float (&s)[3], int (&ix)[3], float v, int kk){
            if (v > s[2]){
                if (v > s[0]){ s[2]=s[1];ix[2]=ix[1]; s[1]=s[0];ix[1]=ix[0]; s[0]=v;ix[0]=kk; }
                else if (v > s[1]){ s[2]=s[1];ix[2]=ix[1]; s[1]=v;ix[1]=kk; }
                else { s[2]=v; ix[2]=kk; }
            }
        };

        #pragma unroll 1
        for (int c = 0; c < NCH_T; c++){
            int buf = c & 1;
            float4 pv[4];
            bool more = (c + 1 < NCH_T);
            if (more){
                const float4* src = (const float4*)(emb + (size_t)(kbase + (c+1)*64)*64);
                #pragma unroll
                for (int j = 0; j < 4; j++) pv[j] = __ldg(&src[j*256 + tid]);
            }

            float acc[8][4];
            #pragma unroll
            for (int nt = 0; nt < 8; nt++){
                int c0 = nt*8 + (lane & 3)*2;
                float2 en2 = *(const float2*)&enS[buf*64 + c0];
                acc[nt][0] = en2.x * -4096.f; acc[nt][1] = en2.y * -4096.f;
                acc[nt][2] = acc[nt][0];      acc[nt][3] = acc[nt][1];
            }

            const uint2* Bb = (const uint2*)(Bs + buf*BSTRIDE);
            #pragma unroll
            for (int ks = 0; ks < 4; ks++){
                #pragma unroll
                for (int nt = 0; nt < 8; nt++){
                    uint2 b = Bb[((nt*4 + ks)*33 + lane)];
                    mma_fp16(acc[nt], Af[ks], b.x, b.y);
                }
            }

            int kk0 = kbase + c*64;
            #pragma unroll
            for (int nt = 0; nt < 8; nt++){
                int c0 = nt*8 + (lane & 3)*2;
                int kA = kk0 + c0, kB = kA + 1;
                if (fmaxf(acc[nt][0], acc[nt][1]) > s0[2]){
                    ins3(s0, ix0, acc[nt][0], kA); ins3(s0, ix0, acc[nt][1], kB);
                }
                if (fmaxf(acc[nt][2], acc[nt][3]) > s1[2]){
                    ins3(s1, ix1, acc[nt][2], kA); ins3(s1, ix1, acc[nt][3], kB);
                }
            }

            if (more){
                uint32_t* BW = Bs + (buf^1)*BSTRIDE;
                #pragma unroll
                for (int j = 0; j < 4; j++){
                    int f = j*256 + tid;
                    int n = f >> 4, k0 = (f & 15)*4;
                    uint32_t u0 = pack2h(pv[j].x*8192.f, pv[j].y*8192.f);
                    uint32_t u1 = pack2h(pv[j].z*8192.f, pv[j].w*8192.f);
                    int nt = n >> 3, ks = k0 >> 4, p = (k0 >> 3) & 1;
                    int Lt = (n & 7)*4 + ((k0 & 7) >> 1);
                    uint32_t* dst = BW + ((nt*4 + ks)*33 + Lt)*2 + p;
                    dst[0] = u0; dst[2] = u1;
                }
                if (tid < 64) enS[(buf^1)*64 + tid] = __ldg(&g_enorm[kbase + (c+1)*64 + tid]);
            }
            BAR(1, 256);
        }

        float q0 = s0[0], q1 = s1[0];
        #pragma unroll
        for (int off = 1; off <= 2; off <<= 1){
            q0 = fmaxf(q0, __shfl_xor_sync(0xFFFFFFFF, q0, off));
            q1 = fmaxf(q1, __shfl_xor_sync(0xFFFFFFFF, q1, off));
        }
        float thr0 = q0 - ACC_TH, thr1 = q1 - ACC_TH;
        float zn0 = znS[r0], zn1 = znS[r0 + 8];

        auto rescore = [&](int rloc, float sv, int idx, float thr, float zn){
            if (sv >= thr){
                const float4* ep = (const float4*)(emb + idx*64);
                float dot = 0.f;
                #pragma unroll 4
                for (int q = 0; q < 16; q++){
                    float4 ev = __ldg(&ep[q]);
                    int d = q*4;
                    dot = fmaf(zS[(d  )*128 + rloc], ev.x, dot);
                    dot = fmaf(zS[(d+1)*128 + rloc], ev.y, dot);
                    dot = fmaf(zS[(d+2)*128 + rloc], ev.z, dot);
                    dot = fmaf(zS[(d+3)*128 + rloc], ev.w, dot);
                }
                float dd = fmaf(-2.f, dot, zn + __ldg(&g_enorm[idx]));
                atomicMin(&g_best[n0 + rloc], packbi(dd, idx));
            }
        };
        #pragma unroll
        for (int j = 0; j < 3; j++){
            rescore(r0,     s0[j], ix0[j], thr0, zn0);
            rescore(r0 + 8, s1[j], ix1[j], thr1, zn1);
        }
    } else {
        // =================== exact FFMA group (128 threads) ===================
        int ltid = tid - 256;
        int tx = ltid & 7, ty = ltid >> 3;          // ty 0..15

        float zn8[8];
        #pragma unroll
        for (int i = 0; i < 4; i++){
            zn8[i]   = znS[ty*4 + i];
            zn8[4+i] = znS[64 + ty*4 + i];
        }

        uint32_t bf_u32 = (uint32_t)__cvta_generic_to_shared(BfS);

        auto issue = [&](int cc, int buf){
            int k0n = kbase + KOFF_F + cc*64;
            uint32_t base = bf_u32 + (uint32_t)buf * (64*BF_CODES*4);
            #pragma unroll
            for (int u = 0; u < 8; u++){
                int un = u*128 + ltid;
                int n = un >> 4, seg = un & 15;
                CP_ASYNC16(base + (uint32_t)(n*BF_CODES + seg*4)*4,
                           emb + (size_t)(k0n + n)*64 + seg*4);
            }
            CP_COMMIT();
        };

        float best8[8]; int idx8[8];
        #pragma unroll
        for (int r = 0; r < 8; r++){ best8[r] = FLT_BIG; idx8[r] = 0; }

        issue(0, 0);

        #pragma unroll 1
        for (int c = 0; c < NCH_F; c++){
            int buf = c & 1;
            BAR(2, 128);                    // all lanes done computing chunk c-1
            if (c + 1 < NCH_F){ issue(c+1, buf^1); CP_WAIT1(); }
            else              { CP_WAIT0(); }
            BAR(2, 128);                    // everyone's chunk-c copies visible

            const float* bf = BfS + buf*(64*BF_CODES);
            float acc[8][8];
            #pragma unroll
            for (int r = 0; r < 8; r++)
                #pragma unroll
                for (int j = 0; j < 8; j++) acc[r][j] = 0.f;

            #pragma unroll 4
            for (int d = 0; d < 64; d++){
                float4 za  = *(const float4*)&zS[d*128 + ty*4];
                float4 zbv = *(const float4*)&zS[d*128 + 64 + ty*4];
                float zr[8] = {za.x, za.y, za.z, za.w, zbv.x, zbv.y, zbv.z, zbv.w};
                #pragma unroll
                for (int j = 0; j < 8; j++){
                    float bv = bf[(tx + 8*j)*BF_CODES + d];
                    #pragma unroll
                    for (int r = 0; r < 8; r++)
                        acc[r][j] = fmaf(zr[r], bv, acc[r][j]);  // d-ascending exact chain
                }
            }

            int k0n = kbase + KOFF_F + c*64;
            #pragma unroll
            for (int j = 0; j < 8; j++){
                int kk = k0n + tx + 8*j;
                float en = __ldg(&g_enorm[kk]);
                #pragma unroll
                for (int r = 0; r < 8; r++){
                    float dd = fmaf(-2.f, acc[r][j], zn8[r] + en);  // exact reference formula
                    if (dd < best8[r]){ best8[r] = dd; idx8[r] = kk; }
                }
            }
        }

        // merge across the 8 tx lanes sharing rows (tie -> lower index)
        #pragma unroll
        for (int off = 4; off > 0; off >>= 1){
            #pragma unroll
            for (int r = 0; r < 8; r++){
                float od = __shfl_down_sync(0xFFFFFFFF, best8[r], off, 8);
                int   oi = __shfl_down_sync(0xFFFFFFFF, idx8[r],  off, 8);
                if (od < best8[r] || (od == best8[r] && oi < idx8[r])){
                    best8[r] = od; idx8[r] = oi;
                }
            }
        }
        if (tx == 0){
            #pragma unroll
            for (int r = 0; r < 8; r++){
                int row = (r < 4) ? (ty*4 + r) : (64 + ty*4 + (r - 4));
                atomicMin(&g_best[n0 + row], packbi(best8[r], idx8[r]));
            }
        }
    }
}

// ---------------------------------------------------------------------------
// K3: gather z_q, straight-through output, loss partial, index output
// ---------------------------------------------------------------------------
__global__ void vq_out(const float* __restrict__ z, const float* __restrict__ emb,
                       float* __restrict__ outz, float* __restrict__ outIdxF, int writeF){
    int tid = threadIdx.x;
    int n0 = blockIdx.x * 64;
    const int b = n0 >> 12; const int hw0 = n0 & 4095;
    const float* zb = z    + b*262144 + hw0;
    float*       ob = outz + b*262144 + hw0;

    __shared__ int idxs[64];
    if (tid < 64){
        int idx = (int)(g_best[n0 + tid] & 0xFFFFFFFFull);
        idxs[tid] = idx;
        if (writeF) outIdxF[n0 + tid] = (float)idx;
    }
    __syncthreads();

    float ls = 0.f;
    for (int i = tid; i < 64*64; i += 256){
        int c = i >> 6, m = i & 63;
        float e  = __ldg(&emb[idxs[m]*64 + c]);
        float zv = zb[c*4096 + m];
        float t  = e - zv;
        ob[c*4096 + m] = zv + t;      // fl(zc + fl(zq - zc)) — STE rounding replicated
        ls = fmaf(t, t, ls);
    }
    __shared__ float red[256];
    red[tid] = ls; __syncthreads();
    for (int s = 128; s > 0; s >>= 1){
        if (tid < s) red[tid] += red[tid + s];
        __syncthreads();
    }
    if (tid == 0) atomicAdd(&g_loss, red[0]);
}

__global__ void vq_fin(float* __restrict__ out, int full){
    if (full){
        float m = g_loss * (1.f / (float)ZQ_ELEMS);
        out[ZQ_ELEMS] = m + 0.25f * m;
    }
}

// ---------------------------------------------------------------------------
extern "C" void kernel_launch(void* const* d_in, const int* in_sizes, int n_in,
                              void* d_out, int out_size){
    const float* z   = (const float*)d_in[0];
    const float* emb = (const float*)d_in[1];
    float* out = (float*)d_out;

    int full = (out_size >= ZQ_ELEMS + 1 + N_TOK) ? 1 : 0;

    cudaFuncSetAttribute(vq_main, cudaFuncAttributeMaxDynamicSharedMemorySize, SMEM_SZ);

    vq_pre<<<N_TOK/256, 256>>>(emb);
    dim3 grid(N_TOK/128, 2);
    vq_main<<<grid, NT, SMEM_SZ>>>(z, emb);
    vq_out<<<N_TOK/64, 256>>>(z, emb, out, full ? (out + ZQ_ELEMS + 1) : out, full);
    vq_fin<<<1, 1>>>(out, full);
}

// round 11
// speedup vs baseline: 2.8813x; 1.1000x over previous
#include <cuda_runtime.h>
#include <cuda_fp16.h>
#include <cstdint>

#define N_TOK    65536
#define KCODES   8192
#define ZQ_ELEMS 4194304
#define NT       256
#define NCH_T    54          // mma chunks (3456 codes)
#define KOFF_F   3456        // ffma region: codes [3456, 4096) = 640 codes
#define NF_CODES 640
#define NSLICE   54          // 54 slices x 12 codes (last partial)
#define SLICE_C  12
#define ACC_TH   0.4096f
#define FLT_BIG  3.402823e38f

// ---- smem layout (bytes) ----
#define SOFF_Z    0          // 32768 : z [d64][m128]
#define SOFF_ZT   32768      // 34816 : z [m128][68] (FFMA path, LDS.128-friendly)
#define SOFF_B16  67584      // 16896 : mma B fp16 frags [buf2]
#define SOFF_EN   84480      // 2*64*4
#define SOFF_ZN   84992      // 128*4
#define SOFF_BF   85504      // 6528 : ffma B fp32 [buf2][12][68]
#define SMEM_SZ   92032
#define BSTRIDE   2112       // uint32 words per mma B buffer
#define BF_STR    68

__device__ float              g_enorm[KCODES];
__device__ unsigned long long g_best[N_TOK];
__device__ float              g_loss;

__device__ __forceinline__ uint32_t pack2h(float lo, float hi){
    uint32_t r; asm("cvt.rn.f16x2.f32 %0, %1, %2;" : "=r"(r) : "f"(hi), "f"(lo)); return r;
}
__device__ __forceinline__ void mma_fp16(float* d, const uint32_t* a, uint32_t b0, uint32_t b1){
    asm volatile("mma.sync.aligned.m16n8k16.row.col.f32.f16.f16.f32 "
        "{%0,%1,%2,%3}, {%4,%5,%6,%7}, {%8,%9}, {%0,%1,%2,%3};"
        : "+f"(d[0]), "+f"(d[1]), "+f"(d[2]), "+f"(d[3])
        : "r"(a[0]), "r"(a[1]), "r"(a[2]), "r"(a[3]), "r"(b0), "r"(b1));
}
__device__ __forceinline__ unsigned long long packbi(float dd, int idx){
    uint32_t u = __float_as_uint(dd);
    u = (u & 0x80000000u) ? ~u : (u | 0x80000000u);
    return ((unsigned long long)u << 32) | (uint32_t)idx;
}
#define CP_ASYNC16(dst, src) asm volatile("cp.async.ca.shared.global [%0], [%1], 16;" :: "r"(dst), "l"(src))
#define CP_COMMIT()  asm volatile("cp.async.commit_group;" ::: "memory")
#define CP_WAIT0()   asm volatile("cp.async.wait_group 0;" ::: "memory")

// ---------------------------------------------------------------------------
__global__ void vq_pre(const float* __restrict__ emb){
    int t = blockIdx.x * 256 + threadIdx.x;
    if (t < KCODES){
        const float4* r = (const float4*)(emb + t*64);
        float s = 0.f;
        #pragma unroll
        for (int i = 0; i < 16; i++){
            float4 v = __ldg(&r[i]);
            s = fmaf(v.x,v.x,s); s = fmaf(v.y,v.y,s); s = fmaf(v.z,v.z,s); s = fmaf(v.w,v.w,s);
        }
        g_enorm[t] = s;
    }
    if (t < N_TOK) g_best[t] = 0xFFFFFFFFFFFFFFFFull;
    if (t == 0) g_loss = 0.f;
}

// ---------------------------------------------------------------------------
// K2: every warp: fp16 HMMA screen (chunks 0..53) + exact-FFMA slice (12 codes)
// per period over codes [3456,4096). Merge via packed atomicMin.
// ---------------------------------------------------------------------------
__global__ __launch_bounds__(NT, 2) void vq_main(const float* __restrict__ z,
                                                 const float* __restrict__ emb){
    extern __shared__ __align__(16) char smem[];
    float*    zS  = (float*)(smem + SOFF_Z);
    float*    zT  = (float*)(smem + SOFF_ZT);
    uint32_t* Bs  = (uint32_t*)(smem + SOFF_B16);
    float*    enS = (float*)(smem + SOFF_EN);
    float*    znS = (float*)(smem + SOFF_ZN);
    float*    BfS = (float*)(smem + SOFF_BF);

    int tid = threadIdx.x, wid = tid >> 5, lane = tid & 31;
    int n0 = blockIdx.x * 128;
    int kbase = blockIdx.y * 4096;
    int kF = kbase + KOFF_F;
    const float* zb = z + (n0 >> 12) * 262144 + (n0 & 4095);

    uint32_t bf_u32 = (uint32_t)__cvta_generic_to_shared(BfS);
    // issue cp.async for ffma slice s into buffer b
    auto issueF = [&](int s, int b){
        if (tid < 192){
            int n = tid >> 4, seg = tid & 15;
            int cg = s*SLICE_C + n;
            int src = (cg < NF_CODES) ? (kF + cg) : kF;     // clamp (guarded at use)
            CP_ASYNC16(bf_u32 + (uint32_t)(b*(SLICE_C*BF_STR) + n*BF_STR + seg*4)*4,
                       emb + (size_t)src*64 + seg*4);
        }
        CP_COMMIT();
    };

    issueF(0, 0);

    for (int i = tid; i < 64*128; i += NT){
        int d = i >> 7, m = i & 127;
        zS[d*128 + m] = zb[d*4096 + m];
    }
    __syncthreads();

    if (tid < 128){
        float s = 0.f;
        #pragma unroll
        for (int d = 0; d < 64; d++){ float v = zS[d*128 + tid]; s = fmaf(v, v, s); }
        znS[tid] = s;
    }
    for (int i = tid; i < 8192; i += NT){
        int m = i >> 6, d = i & 63;
        zT[m*BF_STR + d] = zS[d*128 + m];
    }

    // A fragments (loop-invariant)
    int r0 = wid*16 + (lane >> 2);
    uint32_t Af[4][4];
    #pragma unroll
    for (int ks = 0; ks < 4; ks++){
        int k0 = ks*16 + (lane & 3)*2;
        Af[ks][0] = pack2h(zS[(k0  )*128 + r0  ], zS[(k0+1)*128 + r0  ]);
        Af[ks][1] = pack2h(zS[(k0  )*128 + r0+8], zS[(k0+1)*128 + r0+8]);
        Af[ks][2] = pack2h(zS[(k0+8)*128 + r0  ], zS[(k0+9)*128 + r0  ]);
        Af[ks][3] = pack2h(zS[(k0+8)*128 + r0+8], zS[(k0+9)*128 + r0+8]);
    }

    // produce mma chunk 0 into buffer 0
    {
        const float4* src = (const float4*)(emb + (size_t)kbase*64);
        #pragma unroll
        for (int j = 0; j < 4; j++){
            int f = j*256 + tid;
            float4 v = __ldg(&src[f]);
            int n = f >> 4, k0 = (f & 15)*4;
            uint32_t u0 = pack2h(v.x*8192.f, v.y*8192.f);
            uint32_t u1 = pack2h(v.z*8192.f, v.w*8192.f);
            int nt = n >> 3, ks = k0 >> 4, p = (k0 >> 3) & 1;
            int Lt = (n & 7)*4 + ((k0 & 7) >> 1);
            uint32_t* dst = Bs + ((nt*4 + ks)*33 + Lt)*2 + p;
            dst[0] = u0; dst[2] = u1;
        }
        if (tid < 64) enS[tid] = __ldg(&g_enorm[kbase + tid]);
    }
    CP_WAIT0();
    __syncthreads();

    float zn0 = znS[r0], zn1 = znS[r0 + 8];

    // mma screen state: top-3
    float s0[3], s1[3]; int ix0[3], ix1[3];
    #pragma unroll
    for (int j = 0; j < 3; j++){ s0[j] = -FLT_BIG; s1[j] = -FLT_BIG; ix0[j] = 0; ix1[j] = 0; }
    auto ins3 = [](float (&s)[3], int (&ix)[3], float v, int kk){
        if (v > s[2]){
            if (v > s[0]){ s[2]=s[1];ix[2]=ix[1]; s[1]=s[0];ix[1]=ix[0]; s[0]=v;ix[0]=kk; }
            else if (v > s[1]){ s[2]=s[1];ix[2]=ix[1]; s[1]=v;ix[1]=kk; }
            else { s[2]=v; ix[2]=kk; }
        }
    };

    // ffma state: running exact best per (2 rows); thread covers codes (lane&3)*3+{0..2} per slice
    float fb0 = FLT_BIG, fb1 = FLT_BIG; int fi0 = 0, fi1 = 0;
    const float4* zT4a = (const float4*)(zT + r0*BF_STR);
    const float4* zT4b = (const float4*)(zT + (r0+8)*BF_STR);

    #pragma unroll 1
    for (int c = 0; c < NCH_T; c++){
        int buf = c & 1;
        bool more = (c + 1 < NCH_T);
        float4 pv[4];
        if (more){
            const float4* src = (const float4*)(emb + (size_t)(kbase + (c+1)*64)*64);
            #pragma unroll
            for (int j = 0; j < 4; j++) pv[j] = __ldg(&src[j*256 + tid]);
        }
        if (c + 1 < NSLICE) issueF(c+1, buf^1);

        // ---- mma chunk c ----
        float acc[8][4];
        #pragma unroll
        for (int nt = 0; nt < 8; nt++){
            int c0 = nt*8 + (lane & 3)*2;
            float2 en2 = *(const float2*)&enS[buf*64 + c0];
            acc[nt][0] = en2.x * -4096.f; acc[nt][1] = en2.y * -4096.f;
            acc[nt][2] = acc[nt][0];      acc[nt][3] = acc[nt][1];
        }
        const uint2* Bb = (const uint2*)(Bs + buf*BSTRIDE);
        #pragma unroll
        for (int ks = 0; ks < 4; ks++){
            #pragma unroll
            for (int nt = 0; nt < 8; nt++){
                uint2 b = Bb[(nt*4 + ks)*33 + lane];
                mma_fp16(acc[nt], Af[ks], b.x, b.y);
            }
        }
        int kk0 = kbase + c*64;
        #pragma unroll
        for (int nt = 0; nt < 8; nt++){
            int c0 = nt*8 + (lane & 3)*2;
            int kA = kk0 + c0, kB = kA + 1;
            if (fmaxf(acc[nt][0], acc[nt][1]) > s0[2]){
                ins3(s0, ix0, acc[nt][0], kA); ins3(s0, ix0, acc[nt][1], kB);
            }
            if (fmaxf(acc[nt][2], acc[nt][3]) > s1[2]){
                ins3(s1, ix1, acc[nt][2], kA); ins3(s1, ix1, acc[nt][3], kB);
            }
        }

        // ---- exact ffma slice c (codes kF + c*12 + (lane&3)*3 + {0,1,2}) ----
        if (c < NSLICE){
            const float* bf = BfS + buf*(SLICE_C*BF_STR);
            int cl0 = (lane & 3)*3;
            float fa[3][2];
            #pragma unroll
            for (int j = 0; j < 3; j++){ fa[j][0] = 0.f; fa[j][1] = 0.f; }
            const float4* b0 = (const float4*)(bf + (cl0  )*BF_STR);
            const float4* b1 = (const float4*)(bf + (cl0+1)*BF_STR);
            const float4* b2 = (const float4*)(bf + (cl0+2)*BF_STR);
            #pragma unroll
            for (int dq = 0; dq < 16; dq++){
                float4 za = zT4a[dq], zbv = zT4b[dq];
                float4 e0 = b0[dq], e1 = b1[dq], e2 = b2[dq];
                fa[0][0]=fmaf(za.x,e0.x,fa[0][0]); fa[0][0]=fmaf(za.y,e0.y,fa[0][0]);
                fa[0][0]=fmaf(za.z,e0.z,fa[0][0]); fa[0][0]=fmaf(za.w,e0.w,fa[0][0]);
                fa[0][1]=fmaf(zbv.x,e0.x,fa[0][1]); fa[0][1]=fmaf(zbv.y,e0.y,fa[0][1]);
                fa[0][1]=fmaf(zbv.z,e0.z,fa[0][1]); fa[0][1]=fmaf(zbv.w,e0.w,fa[0][1]);
                fa[1][0]=fmaf(za.x,e1.x,fa[1][0]); fa[1][0]=fmaf(za.y,e1.y,fa[1][0]);
                fa[1][0]=fmaf(za.z,e1.z,fa[1][0]); fa[1][0]=fmaf(za.w,e1.w,fa[1][0]);
                fa[1][1]=fmaf(zbv.x,e1.x,fa[1][1]); fa[1][1]=fmaf(zbv.y,e1.y,fa[1][1]);
                fa[1][1]=fmaf(zbv.z,e1.z,fa[1][1]); fa[1][1]=fmaf(zbv.w,e1.w,fa[1][1]);
                fa[2][0]=fmaf(za.x,e2.x,fa[2][0]); fa[2][0]=fmaf(za.y,e2.y,fa[2][0]);
                fa[2][0]=fmaf(za.z,e2.z,fa[2][0]); fa[2][0]=fmaf(za.w,e2.w,fa[2][0]);
                fa[2][1]=fmaf(zbv.x,e2.x,fa[2][1]); fa[2][1]=fmaf(zbv.y,e2.y,fa[2][1]);
                fa[2][1]=fmaf(zbv.z,e2.z,fa[2][1]); fa[2][1]=fmaf(zbv.w,e2.w,fa[2][1]);
            }
            #pragma unroll
            for (int j = 0; j < 3; j++){
                int cg = c*SLICE_C + cl0 + j;
                if (cg < NF_CODES){
                    int kk = kF + cg;
                    float en = __ldg(&g_enorm[kk]);
                    float d0 = fmaf(-2.f, fa[j][0], zn0 + en);   // exact reference formula
                    float d1 = fmaf(-2.f, fa[j][1], zn1 + en);
                    if (d0 < fb0){ fb0 = d0; fi0 = kk; }
                    if (d1 < fb1){ fb1 = d1; fi1 = kk; }
                }
            }
        }

        // ---- store prefetched mma chunk ----
        if (more){
            uint32_t* BW = Bs + (buf^1)*BSTRIDE;
            #pragma unroll
            for (int j = 0; j < 4; j++){
                int f = j*256 + tid;
                int n = f >> 4, k0 = (f & 15)*4;
                uint32_t u0 = pack2h(pv[j].x*8192.f, pv[j].y*8192.f);
                uint32_t u1 = pack2h(pv[j].z*8192.f, pv[j].w*8192.f);
                int nt = n >> 3, ks = k0 >> 4, p = (k0 >> 3) & 1;
                int Lt = (n & 7)*4 + ((k0 & 7) >> 1);
                uint32_t* dst = BW + ((nt*4 + ks)*33 + Lt)*2 + p;
                dst[0] = u0; dst[2] = u1;
            }
            if (tid < 64) enS[(buf^1)*64 + tid] = __ldg(&g_enorm[kbase + (c+1)*64 + tid]);
        }
        CP_WAIT0();
        __syncthreads();
    }

    // ---- ffma: merge across quad (tie -> lower index), atomicMin ----
    #pragma unroll
    for (int off = 1; off <= 2; off <<= 1){
        float od; int oi;
        od = __shfl_xor_sync(0xFFFFFFFF, fb0, off); oi = __shfl_xor_sync(0xFFFFFFFF, fi0, off);
        if (od < fb0 || (od == fb0 && oi < fi0)){ fb0 = od; fi0 = oi; }
        od = __shfl_xor_sync(0xFFFFFFFF, fb1, off); oi = __shfl_xor_sync(0xFFFFFFFF, fi1, off);
        if (od < fb1 || (od == fb1 && oi < fi1)){ fb1 = od; fi1 = oi; }
    }
    if ((lane & 3) == 0){
        atomicMin(&g_best[n0 + r0],     packbi(fb0, fi0));
        atomicMin(&g_best[n0 + r0 + 8], packbi(fb1, fi1));
    }

    // ---- mma: quad max + exact rescore of in-window top-3 ----
    float q0 = s0[0], q1 = s1[0];
    #pragma unroll
    for (int off = 1; off <= 2; off <<= 1){
        q0 = fmaxf(q0, __shfl_xor_sync(0xFFFFFFFF, q0, off));
        q1 = fmaxf(q1, __shfl_xor_sync(0xFFFFFFFF, q1, off));
    }
    float thr0 = q0 - ACC_TH, thr1 = q1 - ACC_TH;
    auto rescore = [&](int rloc, float sv, int idx, float thr, float zn){
        if (sv >= thr){
            const float4* ep = (const float4*)(emb + idx*64);
            float dot = 0.f;
            #pragma unroll 4
            for (int q = 0; q < 16; q++){
                float4 ev = __ldg(&ep[q]);
                int d = q*4;
                dot = fmaf(zS[(d  )*128 + rloc], ev.x, dot);
                dot = fmaf(zS[(d+1)*128 + rloc], ev.y, dot);
                dot = fmaf(zS[(d+2)*128 + rloc], ev.z, dot);
                dot = fmaf(zS[(d+3)*128 + rloc], ev.w, dot);
            }
            float dd = fmaf(-2.f, dot, zn + __ldg(&g_enorm[idx]));
            atomicMin(&g_best[n0 + rloc], packbi(dd, idx));
        }
    };
    #pragma unroll
    for (int j = 0; j < 3; j++){
        rescore(r0,     s0[j], ix0[j], thr0, zn0);
        rescore(r0 + 8, s1[j], ix1[j], thr1, zn1);
    }
}

// ---------------------------------------------------------------------------
__global__ void vq_out(const float* __restrict__ z, const float* __restrict__ emb,
                       float* __restrict__ outz, float* __restrict__ outIdxF, int writeF){
    int tid = threadIdx.x;
    int n0 = blockIdx.x * 64;
    const int b = n0 >> 12; const int hw0 = n0 & 4095;
    const float* zb = z    + b*262144 + hw0;
    float*       ob = outz + b*262144 + hw0;

    __shared__ int idxs[64];
    if (tid < 64){
        int idx = (int)(g_best[n0 + tid] & 0xFFFFFFFFull);
        idxs[tid] = idx;
        if (writeF) outIdxF[n0 + tid] = (float)idx;
    }
    __syncthreads();

    float ls = 0.f;
    for (int i = tid; i < 64*64; i += 256){
        int c = i >> 6, m = i & 63;
        float e  = __ldg(&emb[idxs[m]*64 + c]);
        float zv = zb[c*4096 + m];
        float t  = e - zv;
        ob[c*4096 + m] = zv + t;      // fl(zc + fl(zq - zc)) — STE rounding replicated
        ls = fmaf(t, t, ls);
    }
    __shared__ float red[256];
    red[tid] = ls; __syncthreads();
    for (int s = 128; s > 0; s >>= 1){
        if (tid < s) red[tid] += red[tid + s];
        __syncthreads();
    }
    if (tid == 0) atomicAdd(&g_loss, red[0]);
}

__global__ void vq_fin(float* __restrict__ out, int full){
    if (full){
        float m = g_loss * (1.f / (float)ZQ_ELEMS);
        out[ZQ_ELEMS] = m + 0.25f * m;
    }
}

// ---------------------------------------------------------------------------
extern "C" void kernel_launch(void* const* d_in, const int* in_sizes, int n_in,
                              void* d_out, int out_size){
    const float* z   = (const float*)d_in[0];
    const float* emb = (const float*)d_in[1];
    float* out = (float*)d_out;

    int full = (out_size >= ZQ_ELEMS + 1 + N_TOK) ? 1 : 0;

    cudaFuncSetAttribute(vq_main, cudaFuncAttributeMaxDynamicSharedMemorySize, SMEM_SZ);

    vq_pre<<<N_TOK/256, 256>>>(emb);
    dim3 grid(N_TOK/128, 2);
    vq_main<<<grid, NT, SMEM_SZ>>>(z, emb);
    vq_out<<<N_TOK/64, 256>>>(z, emb, out, full ? (out + ZQ_ELEMS + 1) : out, full);
    vq_fin<<<1, 1>>>(out, full);
}

// round 12
// speedup vs baseline: 5.5010x; 1.9092x over previous
#include <cuda_runtime.h>
#include <cuda_fp16.h>
#include <cstdint>

#define N_TOK    65536
#define KCODES   8192
#define ZQ_ELEMS 4194304
#define NT       256
#define NCH      128         // all 8192 codes / 64 per chunk
#define ACC_TH   0.4096f
#define FLT_BIG  3.402823e38f

// ---- smem layout (bytes) ----
#define SOFF_Z   0           // 32768 : z tile [d64][m128] fp32
#define SOFF_B   32768       // 16896 : B fp16 frags+enorm [buf2][8448]
#define SOFF_ZN  49664       // 128*4
#define SOFF_IDX 50176       // 128*4
#define SMEM_SZ  50688
#define CHUNK_B  8448        // 8192 frag bytes + 256 enorm bytes

__device__ __align__(16) char g_B16[NCH * CHUNK_B];   // pre-baked fp16 frag image
__device__ float              g_enorm[KCODES];
__device__ float              g_loss;

__device__ __forceinline__ uint32_t pack2h(float lo, float hi){
    uint32_t r; asm("cvt.rn.f16x2.f32 %0, %1, %2;" : "=r"(r) : "f"(hi), "f"(lo)); return r;
}
__device__ __forceinline__ void mma_fp16(float* d, const uint32_t* a, uint32_t b0, uint32_t b1){
    asm volatile("mma.sync.aligned.m16n8k16.row.col.f32.f16.f16.f32 "
        "{%0,%1,%2,%3}, {%4,%5,%6,%7}, {%8,%9}, {%0,%1,%2,%3};"
        : "+f"(d[0]), "+f"(d[1]), "+f"(d[2]), "+f"(d[3])
        : "r"(a[0]), "r"(a[1]), "r"(a[2]), "r"(a[3]), "r"(b0), "r"(b1));
}
#define CP_ASYNC16(dst, src) asm volatile("cp.async.ca.shared.global [%0], [%1], 16;" :: "r"(dst), "l"(src))
#define CP_COMMIT()  asm volatile("cp.async.commit_group;" ::: "memory")
#define CP_WAIT0()   asm volatile("cp.async.wait_group 0;" ::: "memory")

// ---------------------------------------------------------------------------
// K1: bake fp16 frag image (B scaled 2^13) + enorm (sequential fmaf, d asc)
// grid = 128 chunks x 256 threads
// ---------------------------------------------------------------------------
__global__ void vq_pre(const float* __restrict__ emb){
    int c = blockIdx.x, tid = threadIdx.x;
    uint32_t* W = (uint32_t*)(g_B16 + (size_t)c*CHUNK_B);
    #pragma unroll
    for (int j = 0; j < 4; j++){
        int f = j*256 + tid;
        int n = f >> 4, k0 = (f & 15)*4;
        float4 v = __ldg((const float4*)(emb + (size_t)(c*64 + n)*64 + k0));
        uint32_t u0 = pack2h(v.x*8192.f, v.y*8192.f);
        uint32_t u1 = pack2h(v.z*8192.f, v.w*8192.f);
        int nt = n >> 3, ks = k0 >> 4, p = (k0 >> 3) & 1;
        int Lt = (n & 7)*4 + ((k0 & 7) >> 1);
        uint32_t* dst = W + ((nt*4 + ks)*32 + Lt)*2 + p;
        dst[0] = u0; dst[2] = u1;
    }
    if (tid < 64){
        int k = c*64 + tid;
        const float4* r = (const float4*)(emb + (size_t)k*64);
        float s = 0.f;
        #pragma unroll
        for (int i = 0; i < 16; i++){
            float4 v = __ldg(&r[i]);
            s = fmaf(v.x,v.x,s); s = fmaf(v.y,v.y,s); s = fmaf(v.z,v.z,s); s = fmaf(v.w,v.w,s);
        }
        g_enorm[k] = s;
        ((float*)(g_B16 + (size_t)c*CHUNK_B + 8192))[tid] = s;
    }
    if (c == 0 && tid == 0) g_loss = 0.f;
}

// ---------------------------------------------------------------------------
// K2: fp16 HMMA screen over ALL 8192 codes + windowed exact rescore +
//     fused z_q/STE/loss/index output. grid = 512 token tiles.
// ---------------------------------------------------------------------------
__global__ __launch_bounds__(NT, 2) void vq_main(const float* __restrict__ z,
                                                 const float* __restrict__ emb,
                                                 float* __restrict__ outz,
                                                 float* __restrict__ outIdxF, int writeF){
    extern __shared__ __align__(16) char smem[];
    float*    zS    = (float*)(smem + SOFF_Z);
    float*    znS   = (float*)(smem + SOFF_ZN);
    int*      idxSm = (int*)(smem + SOFF_IDX);

    int tid = threadIdx.x, wid = tid >> 5, lane = tid & 31;
    int n0 = blockIdx.x * 128;
    const float* zb = z + (n0 >> 12) * 262144 + (n0 & 4095);

    uint32_t bS = (uint32_t)__cvta_generic_to_shared(smem + SOFF_B);
    auto issueB = [&](int c, int b){
        const char* src = g_B16 + (size_t)c*CHUNK_B;
        uint32_t dst = bS + b*CHUNK_B;
        CP_ASYNC16(dst + tid*32,      src + tid*32);
        CP_ASYNC16(dst + tid*32 + 16, src + tid*32 + 16);
        if (tid < 16) CP_ASYNC16(dst + 8192 + tid*16, src + 8192 + tid*16);
        CP_COMMIT();
    };

    issueB(0, 0);

    for (int i = tid; i < 64*128; i += NT){
        int d = i >> 7, m = i & 127;
        zS[d*128 + m] = zb[d*4096 + m];
    }
    __syncthreads();

    if (tid < 128){
        float s = 0.f;
        #pragma unroll
        for (int d = 0; d < 64; d++){ float v = zS[d*128 + tid]; s = fmaf(v, v, s); }
        znS[tid] = s;
    }

    // A fragments (loop-invariant)
    int r0 = wid*16 + (lane >> 2);
    uint32_t Af[4][4];
    #pragma unroll
    for (int ks = 0; ks < 4; ks++){
        int k0 = ks*16 + (lane & 3)*2;
        Af[ks][0] = pack2h(zS[(k0  )*128 + r0  ], zS[(k0+1)*128 + r0  ]);
        Af[ks][1] = pack2h(zS[(k0  )*128 + r0+8], zS[(k0+1)*128 + r0+8]);
        Af[ks][2] = pack2h(zS[(k0+8)*128 + r0  ], zS[(k0+9)*128 + r0  ]);
        Af[ks][3] = pack2h(zS[(k0+8)*128 + r0+8], zS[(k0+9)*128 + r0+8]);
    }
    CP_WAIT0();
    __syncthreads();

    float zn0 = znS[r0], zn1 = znS[r0 + 8];

    float s0[3], s1[3]; int ix0[3], ix1[3];
    #pragma unroll
    for (int j = 0; j < 3; j++){ s0[j] = -FLT_BIG; s1[j] = -FLT_BIG; ix0[j] = 0; ix1[j] = 0; }
    auto ins3 = [](float (&s)[3], int (&ix)[3], float v, int kk){
        if (v > s[2]){
            if (v > s[0]){ s[2]=s[1];ix[2]=ix[1]; s[1]=s[0];ix[1]=ix[0]; s[0]=v;ix[0]=kk; }
            else if (v > s[1]){ s[2]=s[1];ix[2]=ix[1]; s[1]=v;ix[1]=kk; }
            else { s[2]=v; ix[2]=kk; }
        }
    };

    #pragma unroll 1
    for (int c = 0; c < NCH; c++){
        int buf = c & 1;
        if (c + 1 < NCH) issueB(c+1, buf^1);

        const float* enB = (const float*)(smem + SOFF_B + buf*CHUNK_B + 8192);
        float acc[8][4];
        #pragma unroll
        for (int nt = 0; nt < 8; nt++){
            int c0 = nt*8 + (lane & 3)*2;
            float2 en2 = *(const float2*)&enB[c0];
            acc[nt][0] = en2.x * -4096.f; acc[nt][1] = en2.y * -4096.f;
            acc[nt][2] = acc[nt][0];      acc[nt][3] = acc[nt][1];
        }
        const uint2* Bb = (const uint2*)(smem + SOFF_B + buf*CHUNK_B);
        #pragma unroll
        for (int ks = 0; ks < 4; ks++){
            #pragma unroll
            for (int nt = 0; nt < 8; nt++){
                uint2 b = Bb[(nt*4 + ks)*32 + lane];
                mma_fp16(acc[nt], Af[ks], b.x, b.y);
            }
        }
        int kk0 = c*64;
        #pragma unroll
        for (int nt = 0; nt < 8; nt++){
            int c0 = nt*8 + (lane & 3)*2;
            int kA = kk0 + c0, kB = kA + 1;
            if (fmaxf(acc[nt][0], acc[nt][1]) > s0[2]){
                ins3(s0, ix0, acc[nt][0], kA); ins3(s0, ix0, acc[nt][1], kB);
            }
            if (fmaxf(acc[nt][2], acc[nt][3]) > s1[2]){
                ins3(s1, ix1, acc[nt][2], kA); ins3(s1, ix1, acc[nt][3], kB);
            }
        }
        CP_WAIT0();
        __syncthreads();
    }

    // ---- quad max, windowed exact rescore, local merge ----
    float q0 = s0[0], q1 = s1[0];
    #pragma unroll
    for (int off = 1; off <= 2; off <<= 1){
        q0 = fmaxf(q0, __shfl_xor_sync(0xFFFFFFFF, q0, off));
        q1 = fmaxf(q1, __shfl_xor_sync(0xFFFFFFFF, q1, off));
    }
    float thr0 = q0 - ACC_TH, thr1 = q1 - ACC_TH;

    float rb0 = FLT_BIG, rb1 = FLT_BIG; int ri0 = 0, ri1 = 0;
    auto rescore = [&](int rloc, float sv, int idx, float thr, float zn,
                       float& rb, int& ri){
        if (sv >= thr){
            const float4* ep = (const float4*)(emb + (size_t)idx*64);
            float dot = 0.f;
            #pragma unroll 4
            for (int q = 0; q < 16; q++){
                float4 ev = __ldg(&ep[q]);
                int d = q*4;
                dot = fmaf(zS[(d  )*128 + rloc], ev.x, dot);
                dot = fmaf(zS[(d+1)*128 + rloc], ev.y, dot);
                dot = fmaf(zS[(d+2)*128 + rloc], ev.z, dot);
                dot = fmaf(zS[(d+3)*128 + rloc], ev.w, dot);
            }
            float dd = fmaf(-2.f, dot, zn + __ldg(&g_enorm[idx]));  // exact (R2-validated)
            if (dd < rb || (dd == rb && idx < ri)){ rb = dd; ri = idx; }
        }
    };
    #pragma unroll
    for (int j = 0; j < 3; j++){
        rescore(r0,     s0[j], ix0[j], thr0, zn0, rb0, ri0);
        rescore(r0 + 8, s1[j], ix1[j], thr1, zn1, rb1, ri1);
    }
    #pragma unroll
    for (int off = 1; off <= 2; off <<= 1){
        float od; int oi;
        od = __shfl_xor_sync(0xFFFFFFFF, rb0, off); oi = __shfl_xor_sync(0xFFFFFFFF, ri0, off);
        if (od < rb0 || (od == rb0 && oi < ri0)){ rb0 = od; ri0 = oi; }
        od = __shfl_xor_sync(0xFFFFFFFF, rb1, off); oi = __shfl_xor_sync(0xFFFFFFFF, ri1, off);
        if (od < rb1 || (od == rb1 && oi < ri1)){ rb1 = od; ri1 = oi; }
    }
    if ((lane & 3) == 0){
        idxSm[r0]     = ri0;
        idxSm[r0 + 8] = ri1;
    }
    __syncthreads();

    // ---- fused output: indices, z_q (STE rounding), loss partial ----
    if (writeF && tid < 128) outIdxF[n0 + tid] = (float)idxSm[tid];

    float* ob = outz + (n0 >> 12)*262144 + (n0 & 4095);
    float ls = 0.f;
    for (int i = tid; i < 64*128; i += NT){
        int cc = i >> 7, m = i & 127;
        float e  = __ldg(&emb[(size_t)idxSm[m]*64 + cc]);
        float zv = zS[cc*128 + m];
        float t  = e - zv;                 // fl(zq - zc)
        ob[cc*4096 + m] = zv + t;          // fl(zc + fl(zq - zc)) — STE replicated
        ls = fmaf(t, t, ls);
    }
    // block reduce loss
    __shared__ float red[NT];
    red[tid] = ls; __syncthreads();
    for (int s = 128; s > 0; s >>= 1){
        if (tid < s) red[tid] += red[tid + s];
        __syncthreads();
    }
    if (tid == 0) atomicAdd(&g_loss, red[0]);
}

__global__ void vq_fin(float* __restrict__ out, int full){
    if (full){
        float m = g_loss * (1.f / (float)ZQ_ELEMS);
        out[ZQ_ELEMS] = m + 0.25f * m;
    }
}

// ---------------------------------------------------------------------------
extern "C" void kernel_launch(void* const* d_in, const int* in_sizes, int n_in,
                              void* d_out, int out_size){
    const float* z   = (const float*)d_in[0];
    const float* emb = (const float*)d_in[1];
    float* out = (float*)d_out;

    int full = (out_size >= ZQ_ELEMS + 1 + N_TOK) ? 1 : 0;

    cudaFuncSetAttribute(vq_main, cudaFuncAttributeMaxDynamicSharedMemorySize, SMEM_SZ);

    vq_pre<<<NCH, 256>>>(emb);
    vq_main<<<N_TOK/128, NT, SMEM_SZ>>>(z, emb, out,
                                        full ? (out + ZQ_ELEMS + 1) : out, full);
    vq_fin<<<1, 1>>>(out, full);
}